// round 1
// baseline (speedup 1.0000x reference)
#include <cuda_runtime.h>
#include <math.h>

#define BB 2048
#define DD 2048
#define MAXN (1.0f - 1e-5f)
#define MINN 1e-10f

// ---------------- scratch (no allocations allowed) ----------------
__device__ float g_xp[BB * DD];
__device__ float g_hp[BB * DD];
__device__ float g_xn[BB];
__device__ float g_hn[BB];
__device__ float g_rphn[BB];
__device__ float g_G0[BB * DD];  // hp @ w_z
__device__ float g_G1[BB * DD];  // hp @ w_r
__device__ float g_G2[BB * DD];  // xp @ u_z
__device__ float g_G3[BB * DD];  // xp @ u_r
__device__ float g_G4[BB * DD];  // rph @ w_h
__device__ float g_z[BB * DD];
__device__ float g_r[BB * DD];
__device__ float g_rph[BB * DD];
__device__ float g_ht[BB * DD];

// ---------------- block-wide multi-value reduction ----------------
template <int NV>
__device__ __forceinline__ void block_reduce(float (&v)[NV]) {
    __shared__ float sm[NV * 8];
    __syncthreads();  // protect smem reuse across calls
    int lane = threadIdx.x & 31, w = threadIdx.x >> 5;
#pragma unroll
    for (int i = 0; i < NV; i++) {
        float x = v[i];
#pragma unroll
        for (int o = 16; o > 0; o >>= 1) x += __shfl_down_sync(0xffffffffu, x, o);
        if (lane == 0) sm[i * 8 + w] = x;
    }
    __syncthreads();
    if (threadIdx.x == 0) {
#pragma unroll
        for (int i = 0; i < NV; i++) {
            float s = 0.f;
#pragma unroll
            for (int j = 0; j < 8; j++) s += sm[i * 8 + j];
            sm[i * 8] = s;
        }
    }
    __syncthreads();
#pragma unroll
    for (int i = 0; i < NV; i++) v[i] = sm[i * 8];
}

// vector = coef * base, s2 = coef^2 * sum(base^2). Apply Poincare _proj.
__device__ __forceinline__ void proj_coef(float& coef, float& s2) {
    float n = sqrtf(fmaxf(s2, MINN));
    if (n > MAXN) {
        float f = MAXN / n;
        coef *= f;
        s2 *= f * f;
    }
}

__device__ __forceinline__ float artanh_c(float x) {
    return atanhf(fminf(x, MAXN));
}

// ---------------- K0: proj inputs + store row norms ----------------
__global__ void proj_norm_kernel(const float* __restrict__ hx, const float* __restrict__ hd) {
    int row = blockIdx.x;
    const float* src = blockIdx.y ? hd : hx;
    float* dst = blockIdx.y ? g_hp : g_xp;
    float* nd = blockIdx.y ? g_hn : g_xn;
    const float* p = src + (size_t)row * DD;
    float acc[1] = {0.f};
    for (int j = threadIdx.x; j < DD; j += blockDim.x) {
        float v = p[j];
        acc[0] += v * v;
    }
    block_reduce<1>(acc);
    float n = sqrtf(fmaxf(acc[0], MINN));
    float sc = (n > MAXN) ? (MAXN / n) : 1.f;
    float* o = dst + (size_t)row * DD;
    for (int j = threadIdx.x; j < DD; j += blockDim.x) o[j] = p[j] * sc;
    if (threadIdx.x == 0) nd[row] = fminf(n, MAXN);
}

// ---------------- SGEMM: C[2048,2048] = A @ B, all row-major ----------------
struct GemmArgs {
    const float* A[4];
    const float* Bm[4];
    float* C[4];
};

__global__ void __launch_bounds__(256, 2) sgemm_kernel(GemmArgs ga) {
    const float* __restrict__ A = ga.A[blockIdx.z];
    const float* __restrict__ B = ga.Bm[blockIdx.z];
    float* __restrict__ C = ga.C[blockIdx.z];
    const int K = DD, N = DD;

    __shared__ float As[16][128];
    __shared__ float Bs[16][128];

    int tid = threadIdx.x;
    int tx = tid & 15, ty = tid >> 4;
    int m0 = blockIdx.y * 128, n0 = blockIdx.x * 128;

    int ar0 = tid >> 2;              // A tile row (0..63), second chunk +64
    int ac0 = (tid & 3) * 4;         // A tile col (float index)
    int br0 = tid >> 5;              // B tile row (0..7), second chunk +8
    int bc0 = (tid & 31) * 4;        // B tile col

    const float* Ap0 = A + (size_t)(m0 + ar0) * K + ac0;
    const float* Ap1 = A + (size_t)(m0 + ar0 + 64) * K + ac0;
    const float* Bp0 = B + (size_t)br0 * N + n0 + bc0;
    const float* Bp1 = B + (size_t)(br0 + 8) * N + n0 + bc0;

    float acc[8][8];
#pragma unroll
    for (int i = 0; i < 8; i++)
#pragma unroll
        for (int j = 0; j < 8; j++) acc[i][j] = 0.f;

    float4 a0 = *(const float4*)(Ap0);
    float4 a1 = *(const float4*)(Ap1);
    float4 b0 = *(const float4*)(Bp0);
    float4 b1 = *(const float4*)(Bp1);

    for (int kt = 0; kt < K; kt += 16) {
        // stage into smem
        As[ac0 + 0][ar0] = a0.x; As[ac0 + 1][ar0] = a0.y;
        As[ac0 + 2][ar0] = a0.z; As[ac0 + 3][ar0] = a0.w;
        As[ac0 + 0][ar0 + 64] = a1.x; As[ac0 + 1][ar0 + 64] = a1.y;
        As[ac0 + 2][ar0 + 64] = a1.z; As[ac0 + 3][ar0 + 64] = a1.w;
        *(float4*)&Bs[br0][bc0] = b0;
        *(float4*)&Bs[br0 + 8][bc0] = b1;
        __syncthreads();

        // prefetch next tile while computing
        if (kt + 16 < K) {
            a0 = *(const float4*)(Ap0 + kt + 16);
            a1 = *(const float4*)(Ap1 + kt + 16);
            b0 = *(const float4*)(Bp0 + (size_t)(kt + 16) * N);
            b1 = *(const float4*)(Bp1 + (size_t)(kt + 16) * N);
        }

#pragma unroll
        for (int k = 0; k < 16; k++) {
            float4 av0 = *(const float4*)&As[k][ty * 4];
            float4 av1 = *(const float4*)&As[k][64 + ty * 4];
            float4 bv0 = *(const float4*)&Bs[k][tx * 4];
            float4 bv1 = *(const float4*)&Bs[k][64 + tx * 4];
            float ar[8] = {av0.x, av0.y, av0.z, av0.w, av1.x, av1.y, av1.z, av1.w};
            float br[8] = {bv0.x, bv0.y, bv0.z, bv0.w, bv1.x, bv1.y, bv1.z, bv1.w};
#pragma unroll
            for (int i = 0; i < 8; i++)
#pragma unroll
                for (int j = 0; j < 8; j++) acc[i][j] = fmaf(ar[i], br[j], acc[i][j]);
        }
        __syncthreads();
    }

#pragma unroll
    for (int i = 0; i < 8; i++) {
        int row = m0 + ((i < 4) ? (ty * 4 + i) : (64 + ty * 4 + i - 4));
        float4 c0 = make_float4(acc[i][0], acc[i][1], acc[i][2], acc[i][3]);
        float4 c1 = make_float4(acc[i][4], acc[i][5], acc[i][6], acc[i][7]);
        *(float4*)&C[(size_t)row * N + n0 + tx * 4] = c0;
        *(float4*)&C[(size_t)row * N + n0 + 64 + tx * 4] = c1;
    }
}

// ---------------- combine: transition(W,h,U,x,b) [+ sigmoid(logmap)] ----------------
// out_i = f( fw*Wh_i + fu*Ux_i + fb*b_i ), all scalars from row reductions.
__global__ void combine_kernel(const float* __restrict__ Wh, const float* __restrict__ Ux,
                               const float* __restrict__ bias,
                               const float* __restrict__ nhArr, const float* __restrict__ nxArr,
                               float* __restrict__ out, int do_gate) {
    int row = blockIdx.x;
    const float* wr = Wh + (size_t)row * DD;
    const float* ur = Ux + (size_t)row * DD;
    float v[6] = {0.f, 0.f, 0.f, 0.f, 0.f, 0.f};
    for (int j = threadIdx.x; j < DD; j += blockDim.x) {
        float w = wr[j], u = ur[j], b = bias[j];
        v[0] += w * w;  // |Wh|^2
        v[1] += u * u;  // |Ux|^2
        v[2] += w * u;  // Wh.Ux
        v[3] += w * b;  // Wh.b
        v[4] += u * b;  // Ux.b
        v[5] += b * b;  // |b|^2
    }
    block_reduce<6>(v);

    float hn = nhArr[row], xn = nxArr[row];

    // mob_mat_mul epilogues (coef on raw GEMM rows)
    float Mw = sqrtf(fmaxf(v[0], MINN));
    float cu = tanhf(Mw / hn * artanh_c(hn)) / Mw;
    float su = cu * cu * v[0];
    proj_coef(cu, su);

    float Mu = sqrtf(fmaxf(v[1], MINN));
    float cv = tanhf(Mu / xn * artanh_c(xn)) / Mu;
    float sv = cv * cv * v[1];
    proj_coef(cv, sv);

    // mob_add(u, v)
    float uv = cu * cv * v[2];
    float a = 1.f + 2.f * uv + sv;
    float c = 1.f - su;
    float den = fmaxf(1.f + 2.f * uv + su * sv, MINN);
    float aw = a * cu / den, au = c * cv / den;
    float q2 = aw * aw * v[0] + 2.f * aw * au * v[2] + au * au * v[1];
    {
        float n = sqrtf(fmaxf(q2, MINN));
        if (n > MAXN) { float f = MAXN / n; aw *= f; au *= f; q2 *= f * f; }
    }

    // mob_add(q, b)
    float qb = aw * v[3] + au * v[4];
    float b2 = v[5];
    float A2 = 1.f + 2.f * qb + b2;
    float C2 = 1.f - q2;
    float den2 = fmaxf(1.f + 2.f * qb + q2 * b2, MINN);
    float fw = A2 * aw / den2, fu = A2 * au / den2, fb = C2 / den2;
    float f2 = fw * fw * v[0] + fu * fu * v[1] + fb * fb * v[5] +
               2.f * fw * fu * v[2] + 2.f * fw * fb * v[3] + 2.f * fu * fb * v[4];
    {
        float n = sqrtf(fmaxf(f2, MINN));
        if (n > MAXN) { float f = MAXN / n; fw *= f; fu *= f; fb *= f; f2 *= f * f; }
    }

    float* o = out + (size_t)row * DD;
    if (do_gate) {
        float fn = sqrtf(fmaxf(f2, MINN));
        float lg = artanh_c(fn) / fn;
        for (int j = threadIdx.x; j < DD; j += blockDim.x) {
            float t = lg * (fw * wr[j] + fu * ur[j] + fb * bias[j]);
            o[j] = 1.f / (1.f + expf(-t));
        }
    } else {
        for (int j = threadIdx.x; j < DD; j += blockDim.x)
            o[j] = fw * wr[j] + fu * ur[j] + fb * bias[j];
    }
}

// ---------------- r_point_h = exp0( log0(hp) * r ) ----------------
__global__ void rpoint_kernel() {
    int row = blockIdx.x;
    const float* hp = g_hp + (size_t)row * DD;
    const float* r = g_r + (size_t)row * DD;
    float hn = g_hn[row];
    float ch = artanh_c(hn) / hn;

    float v[1] = {0.f};
    for (int j = threadIdx.x; j < DD; j += blockDim.x) {
        float t = hp[j] * r[j];
        v[0] += t * t;
    }
    block_reduce<1>(v);

    float s2 = ch * ch * v[0];
    float nv = sqrtf(fmaxf(s2, MINN));
    float cpf = tanhf(nv) / nv * ch;     // coef on hp_i * r_i
    float o2 = cpf * cpf * v[0];
    float on = sqrtf(fmaxf(o2, MINN));
    if (on > MAXN) { cpf *= MAXN / on; on = MAXN; }

    float* o = g_rph + (size_t)row * DD;
    for (int j = threadIdx.x; j < DD; j += blockDim.x) o[j] = cpf * hp[j] * r[j];
    if (threadIdx.x == 0) g_rphn[row] = on;
}

// ---------------- final: new_h = hp (+) exp0( log0(mob_add(-hp,ht)) * z ) ----------------
__global__ void final_kernel(float* __restrict__ out) {
    int row = blockIdx.x;
    const float* hp = g_hp + (size_t)row * DD;
    const float* ht = g_ht + (size_t)row * DD;
    const float* z = g_z + (size_t)row * DD;
    float hn = g_hn[row];
    float u2 = hn * hn;

    // pass 1: mob_add(-hp, ht)
    float v[2] = {0.f, 0.f};
    for (int j = threadIdx.x; j < DD; j += blockDim.x) {
        float h = hp[j], t = ht[j];
        v[0] += h * t;  // hp.ht
        v[1] += t * t;  // |ht|^2
    }
    block_reduce<2>(v);

    float uv = -v[0], v2 = v[1];
    float a = 1.f + 2.f * uv + v2;
    float c = 1.f - u2;
    float den = fmaxf(1.f + 2.f * uv + u2 * v2, MINN);
    float mh = -a / den, mt = c / den;  // m = mh*hp + mt*ht
    float m2 = mh * mh * u2 + 2.f * mh * mt * v[0] + mt * mt * v[1];
    {
        float n = sqrtf(fmaxf(m2, MINN));
        if (n > MAXN) { float f = MAXN / n; mh *= f; mt *= f; m2 *= f * f; }
    }
    float mn = sqrtf(fmaxf(m2, MINN));
    float cm = artanh_c(mn) / mn;  // log-map coef

    // pass 2: reductions for exp0(cm * z * m) and mob_add(hp, .)
    float w[2] = {0.f, 0.f};
    for (int j = threadIdx.x; j < DD; j += blockDim.x) {
        float m = mh * hp[j] + mt * ht[j];
        float zm = z[j] * m;
        w[0] += zm * zm;
        w[1] += zm * hp[j];
    }
    block_reduce<2>(w);

    float sv2 = cm * cm * w[0];
    float nv = sqrtf(fmaxf(sv2, MINN));
    float cp = tanhf(nv) / nv * cm;  // p_i = cp * z_i * m_i
    float p2 = cp * cp * w[0];
    {
        float n = sqrtf(fmaxf(p2, MINN));
        if (n > MAXN) { float f = MAXN / n; cp *= f; p2 *= f * f; }
    }

    // mob_add(hp, p)
    float uv2 = cp * w[1];
    float A = 1.f + 2.f * uv2 + p2;
    float C = 1.f - u2;
    float den3 = fmaxf(1.f + 2.f * uv2 + u2 * p2, MINN);
    float chh = A / den3;            // coef on hp
    float cpp = C * cp / den3;       // coef on z*m
    float o2 = chh * chh * u2 + 2.f * chh * cpp * w[1] + cpp * cpp * w[0];
    {
        float n = sqrtf(fmaxf(o2, MINN));
        if (n > MAXN) { float f = MAXN / n; chh *= f; cpp *= f; }
    }

    float* o = out + (size_t)row * DD;
    for (int j = threadIdx.x; j < DD; j += blockDim.x) {
        float m = mh * hp[j] + mt * ht[j];
        o[j] = chh * hp[j] + cpp * z[j] * m;
    }
}

// ---------------- launch ----------------
extern "C" void kernel_launch(void* const* d_in, const int* in_sizes, int n_in,
                              void* d_out, int out_size) {
    (void)in_sizes; (void)n_in; (void)out_size;
    const float* hyp_x = (const float*)d_in[0];
    const float* hidden = (const float*)d_in[1];
    const float* w_z = (const float*)d_in[2];
    const float* w_r = (const float*)d_in[3];
    const float* w_h = (const float*)d_in[4];
    const float* u_z = (const float*)d_in[5];
    const float* u_r = (const float*)d_in[6];
    const float* b_z = (const float*)d_in[7];
    const float* b_r = (const float*)d_in[8];
    const float* b_h = (const float*)d_in[9];
    float* out = (float*)d_out;

    float *xp, *hp, *G0, *G1, *G2, *G3, *G4, *zz, *rr, *rph, *ht, *xn, *hn, *rphn;
    cudaGetSymbolAddress((void**)&xp, g_xp);
    cudaGetSymbolAddress((void**)&hp, g_hp);
    cudaGetSymbolAddress((void**)&G0, g_G0);
    cudaGetSymbolAddress((void**)&G1, g_G1);
    cudaGetSymbolAddress((void**)&G2, g_G2);
    cudaGetSymbolAddress((void**)&G3, g_G3);
    cudaGetSymbolAddress((void**)&G4, g_G4);
    cudaGetSymbolAddress((void**)&zz, g_z);
    cudaGetSymbolAddress((void**)&rr, g_r);
    cudaGetSymbolAddress((void**)&rph, g_rph);
    cudaGetSymbolAddress((void**)&ht, g_ht);
    cudaGetSymbolAddress((void**)&xn, g_xn);
    cudaGetSymbolAddress((void**)&hn, g_hn);
    cudaGetSymbolAddress((void**)&rphn, g_rphn);

    // 1. project inputs, record norms
    proj_norm_kernel<<<dim3(BB, 2), 256>>>(hyp_x, hidden);

    // 2. four independent GEMMs in one batched launch
    GemmArgs ga;
    ga.A[0] = hp; ga.Bm[0] = w_z; ga.C[0] = G0;
    ga.A[1] = hp; ga.Bm[1] = w_r; ga.C[1] = G1;
    ga.A[2] = xp; ga.Bm[2] = u_z; ga.C[2] = G2;
    ga.A[3] = xp; ga.Bm[3] = u_r; ga.C[3] = G3;
    sgemm_kernel<<<dim3(16, 16, 4), 256>>>(ga);

    // 3. gates z and r (sigmoid o logmap o transition)
    combine_kernel<<<BB, 256>>>(G0, G2, b_z, hn, xn, zz, 1);
    combine_kernel<<<BB, 256>>>(G1, G3, b_r, hn, xn, rr, 1);

    // 4. r_point_h
    rpoint_kernel<<<BB, 256>>>();

    // 5. GEMM rph @ w_h
    GemmArgs gh;
    gh.A[0] = rph; gh.Bm[0] = w_h; gh.C[0] = G4;
    gh.A[1] = rph; gh.Bm[1] = w_h; gh.C[1] = G4;
    gh.A[2] = rph; gh.Bm[2] = w_h; gh.C[2] = G4;
    gh.A[3] = rph; gh.Bm[3] = w_h; gh.C[3] = G4;
    sgemm_kernel<<<dim3(16, 16, 1), 256>>>(gh);

    // 6. h_tilde (transition, no sigmoid/logmap) — reuses G3 = xp@u_r per reference
    combine_kernel<<<BB, 256>>>(G4, G3, b_h, rphn, xn, ht, 0);

    // 7. new_h
    final_kernel<<<BB, 256>>>(out);
}

// round 3
// speedup vs baseline: 1.8830x; 1.8830x over previous
#include <cuda_runtime.h>
#include <cuda_bf16.h>
#include <math.h>
#include <stdint.h>

#define BB 2048
#define DD 2048
#define MAXN (1.0f - 1e-5f)
#define MINN 1e-10f

// ---------------- scratch (no allocations allowed) ----------------
__device__ float g_xp[BB * DD];
__device__ float g_hp[BB * DD];
__device__ float g_xn[BB];
__device__ float g_hn[BB];
__device__ float g_rphn[BB];
__device__ float g_G0[BB * DD];  // hp @ w_z
__device__ float g_G1[BB * DD];  // hp @ w_r
__device__ float g_G2[BB * DD];  // xp @ u_z
__device__ float g_G3[BB * DD];  // xp @ u_r
__device__ float g_G4[BB * DD];  // rph @ w_h
__device__ float g_z[BB * DD];
__device__ float g_r[BB * DD];
__device__ float g_rph[BB * DD];
__device__ float g_ht[BB * DD];

// =================== helpers ===================
__device__ __forceinline__ uint32_t smem_u32(const void* p) {
    uint32_t a;
    asm("{ .reg .u64 t; cvta.to.shared.u64 t, %1; cvt.u32.u64 %0, t; }" : "=r"(a) : "l"(p));
    return a;
}

__device__ __forceinline__ void cvt_hi_lo(float x, float y, uint32_t& h, uint32_t& l) {
    __nv_bfloat16 hx = __float2bfloat16_rn(x);
    __nv_bfloat16 hy = __float2bfloat16_rn(y);
    float lx = x - __bfloat162float(hx);
    float ly = y - __bfloat162float(hy);
    __nv_bfloat162 hp2;
    hp2.x = hx; hp2.y = hy;
    h = *reinterpret_cast<uint32_t*>(&hp2);
    __nv_bfloat162 lp = __floats2bfloat162_rn(lx, ly);
    l = *reinterpret_cast<uint32_t*>(&lp);
}

#define STS128(addr, r0, r1, r2, r3) \
    asm volatile("st.shared.v4.b32 [%0], {%1,%2,%3,%4};" \
                 :: "r"(addr), "r"(r0), "r"(r1), "r"(r2), "r"(r3) : "memory")

__device__ __forceinline__ void ldmatrix_x4(uint32_t* r, uint32_t addr) {
    asm volatile("ldmatrix.sync.aligned.m8n8.x4.shared.b16 {%0,%1,%2,%3}, [%4];"
                 : "=r"(r[0]), "=r"(r[1]), "=r"(r[2]), "=r"(r[3]) : "r"(addr));
}
__device__ __forceinline__ void ldmatrix_x4_t(uint32_t* r, uint32_t addr) {
    asm volatile("ldmatrix.sync.aligned.m8n8.x4.trans.shared.b16 {%0,%1,%2,%3}, [%4];"
                 : "=r"(r[0]), "=r"(r[1]), "=r"(r[2]), "=r"(r[3]) : "r"(addr));
}
__device__ __forceinline__ void mma16816(float* d, const uint32_t* a, uint32_t b0, uint32_t b1) {
    asm volatile(
        "mma.sync.aligned.m16n8k16.row.col.f32.bf16.bf16.f32 "
        "{%0,%1,%2,%3}, {%4,%5,%6,%7}, {%8,%9}, {%0,%1,%2,%3};"
        : "+f"(d[0]), "+f"(d[1]), "+f"(d[2]), "+f"(d[3])
        : "r"(a[0]), "r"(a[1]), "r"(a[2]), "r"(a[3]), "r"(b0), "r"(b1));
}

// =================== bf16x3 mma.sync GEMM ===================
// C[2048,2048] = A @ B fp32 row-major. 128x128 CTA tile, KC=32, double buffer.
struct GemmArgs {
    const float* A[4];
    const float* Bm[4];
    float* C[4];
};

#define KC 32
#define NCH (DD / KC)
// smem layout per buffer: A_hi 128x40h(80B)=10240, A_lo 10240,
// B_hi 32x136h(272B)=8704, B_lo 8704 -> 37888 per buf
#define BUF_SZ 37888u
#define AHI(s) ((uint32_t)(s) * BUF_SZ)
#define ALO(s) (AHI(s) + 10240u)
#define BHI(s) (AHI(s) + 20480u)
#define BLO(s) (AHI(s) + 29184u)
#define SMEM_BYTES (2 * 37888)
#define A_PITCH 80
#define B_PITCH 272

__global__ void __launch_bounds__(256, 1) mma_gemm_kernel(GemmArgs ga) {
    extern __shared__ char smem[];
    const float* __restrict__ A = ga.A[blockIdx.z];
    const float* __restrict__ Bg = ga.Bm[blockIdx.z];
    float* __restrict__ C = ga.C[blockIdx.z];
    const int m0 = blockIdx.y * 128, n0 = blockIdx.x * 128;
    const uint32_t sbase = smem_u32(smem);
    const int tid = threadIdx.x, wid = tid >> 5, lane = tid & 31;
    const int wm = wid >> 2, wn = wid & 3;  // warp tile: rows wm*64, cols wn*32

    // staging: A row = tid>>1, k quarter = (tid&1)*16 ; B krow = tid>>3, n quarter = (tid&7)*16
    const int ar = tid >> 1, akq = (tid & 1) * 16;
    const int bk = tid >> 3, bnq = (tid & 7) * 16;
    const float* agp = A + (size_t)(m0 + ar) * DD + akq;
    const float* bgp = Bg + (size_t)bk * DD + n0 + bnq;

    float acc[4][4][4];
#pragma unroll
    for (int i = 0; i < 4; i++)
#pragma unroll
        for (int j = 0; j < 4; j++)
#pragma unroll
            for (int e = 0; e < 4; e++) acc[i][j][e] = 0.f;

    float4 areg[4], breg[4];

    // ---- load chunk 0 ----
#pragma unroll
    for (int q = 0; q < 4; q++) {
        areg[q] = *(const float4*)(agp + q * 4);
        breg[q] = *(const float4*)(bgp + q * 4);
    }
    // ---- convert+store chunk 0 into buf 0 ----
    {
        uint32_t h[8], l[8];
#pragma unroll
        for (int q = 0; q < 4; q++) {
            cvt_hi_lo(areg[q].x, areg[q].y, h[q * 2], l[q * 2]);
            cvt_hi_lo(areg[q].z, areg[q].w, h[q * 2 + 1], l[q * 2 + 1]);
        }
        uint32_t ad = sbase + AHI(0) + ar * A_PITCH + akq * 2;
        STS128(ad, h[0], h[1], h[2], h[3]);
        STS128(ad + 16, h[4], h[5], h[6], h[7]);
        uint32_t ad2 = ad + (ALO(0) - AHI(0));
        STS128(ad2, l[0], l[1], l[2], l[3]);
        STS128(ad2 + 16, l[4], l[5], l[6], l[7]);
#pragma unroll
        for (int q = 0; q < 4; q++) {
            cvt_hi_lo(breg[q].x, breg[q].y, h[q * 2], l[q * 2]);
            cvt_hi_lo(breg[q].z, breg[q].w, h[q * 2 + 1], l[q * 2 + 1]);
        }
        uint32_t bd = sbase + BHI(0) + bk * B_PITCH + bnq * 2;
        STS128(bd, h[0], h[1], h[2], h[3]);
        STS128(bd + 16, h[4], h[5], h[6], h[7]);
        uint32_t bd2 = bd + (BLO(0) - BHI(0));
        STS128(bd2, l[0], l[1], l[2], l[3]);
        STS128(bd2 + 16, l[4], l[5], l[6], l[7]);
    }
    __syncthreads();

    // fragment address components (per lane)
    const int frow = lane & 15;        // row-in-16 for both A and B ldmatrix
    const int fcol8 = (lane >> 4) * 8; // 8-col half select

    for (int i = 0; i < NCH; i++) {
        const int s = i & 1;
        const bool has_next = (i + 1) < NCH;
        if (has_next) {
            int kc = (i + 1) * KC;
#pragma unroll
            for (int q = 0; q < 4; q++) {
                areg[q] = *(const float4*)(agp + kc + q * 4);
                breg[q] = *(const float4*)(bgp + (size_t)kc * DD + q * 4);
            }
        }

        // ---- compute on buffer s ----
#pragma unroll
        for (int ks = 0; ks < 2; ks++) {
            uint32_t a_h[4][4], a_l[4][4];
            uint32_t b_h[2][4], b_l[2][4];
            uint32_t acol = (uint32_t)(ks * 16 + fcol8) * 2;
#pragma unroll
            for (int mt = 0; mt < 4; mt++) {
                uint32_t rbase = (uint32_t)(wm * 64 + mt * 16 + frow) * A_PITCH + acol;
                ldmatrix_x4(a_h[mt], sbase + AHI(s) + rbase);
                ldmatrix_x4(a_l[mt], sbase + ALO(s) + rbase);
            }
            uint32_t brow = (uint32_t)(ks * 16 + frow) * B_PITCH;
#pragma unroll
            for (int nh = 0; nh < 2; nh++) {
                uint32_t bco = (uint32_t)(wn * 32 + nh * 16 + fcol8) * 2;
                ldmatrix_x4_t(b_h[nh], sbase + BHI(s) + brow + bco);
                ldmatrix_x4_t(b_l[nh], sbase + BLO(s) + brow + bco);
            }
#pragma unroll
            for (int mt = 0; mt < 4; mt++) {
#pragma unroll
                for (int j = 0; j < 4; j++) {
                    int nh = j >> 1, sb = (j & 1) * 2;
                    mma16816(acc[mt][j], a_h[mt], b_h[nh][sb], b_h[nh][sb + 1]);
                    mma16816(acc[mt][j], a_h[mt], b_l[nh][sb], b_l[nh][sb + 1]);
                    mma16816(acc[mt][j], a_l[mt], b_h[nh][sb], b_h[nh][sb + 1]);
                }
            }
        }

        // ---- convert+store next chunk into buffer s^1 ----
        if (has_next) {
            int ns = s ^ 1;
            uint32_t h[8], l[8];
#pragma unroll
            for (int q = 0; q < 4; q++) {
                cvt_hi_lo(areg[q].x, areg[q].y, h[q * 2], l[q * 2]);
                cvt_hi_lo(areg[q].z, areg[q].w, h[q * 2 + 1], l[q * 2 + 1]);
            }
            uint32_t ad = sbase + AHI(ns) + ar * A_PITCH + akq * 2;
            STS128(ad, h[0], h[1], h[2], h[3]);
            STS128(ad + 16, h[4], h[5], h[6], h[7]);
            uint32_t ad2 = ad + 10240u;
            STS128(ad2, l[0], l[1], l[2], l[3]);
            STS128(ad2 + 16, l[4], l[5], l[6], l[7]);
#pragma unroll
            for (int q = 0; q < 4; q++) {
                cvt_hi_lo(breg[q].x, breg[q].y, h[q * 2], l[q * 2]);
                cvt_hi_lo(breg[q].z, breg[q].w, h[q * 2 + 1], l[q * 2 + 1]);
            }
            uint32_t bd = sbase + BHI(ns) + bk * B_PITCH + bnq * 2;
            STS128(bd, h[0], h[1], h[2], h[3]);
            STS128(bd + 16, h[4], h[5], h[6], h[7]);
            uint32_t bd2 = bd + 8704u;
            STS128(bd2, l[0], l[1], l[2], l[3]);
            STS128(bd2 + 16, l[4], l[5], l[6], l[7]);
        }
        __syncthreads();
    }

    // ---- epilogue ----
#pragma unroll
    for (int mt = 0; mt < 4; mt++) {
#pragma unroll
        for (int j = 0; j < 4; j++) {
            int row = m0 + wm * 64 + mt * 16 + (lane >> 2);
            int col = n0 + wn * 32 + j * 8 + (lane & 3) * 2;
            float2 v0 = make_float2(acc[mt][j][0], acc[mt][j][1]);
            float2 v1 = make_float2(acc[mt][j][2], acc[mt][j][3]);
            *(float2*)(C + (size_t)row * DD + col) = v0;
            *(float2*)(C + (size_t)(row + 8) * DD + col) = v1;
        }
    }
}

// =================== elementwise kernels ===================
template <int NV>
__device__ __forceinline__ void block_reduce(float (&v)[NV]) {
    __shared__ float sm[NV * 8];
    __syncthreads();
    int lane = threadIdx.x & 31, w = threadIdx.x >> 5;
#pragma unroll
    for (int i = 0; i < NV; i++) {
        float x = v[i];
#pragma unroll
        for (int o = 16; o > 0; o >>= 1) x += __shfl_down_sync(0xffffffffu, x, o);
        if (lane == 0) sm[i * 8 + w] = x;
    }
    __syncthreads();
    if (threadIdx.x == 0) {
#pragma unroll
        for (int i = 0; i < NV; i++) {
            float s = 0.f;
#pragma unroll
            for (int j = 0; j < 8; j++) s += sm[i * 8 + j];
            sm[i * 8] = s;
        }
    }
    __syncthreads();
#pragma unroll
    for (int i = 0; i < NV; i++) v[i] = sm[i * 8];
}

__device__ __forceinline__ float artanh_c(float x) { return atanhf(fminf(x, MAXN)); }

__global__ void __launch_bounds__(256) proj_norm_kernel(const float* __restrict__ hx,
                                                        const float* __restrict__ hd) {
    int row = blockIdx.x;
    const float* src = blockIdx.y ? hd : hx;
    float* dst = blockIdx.y ? g_hp : g_xp;
    float* nd = blockIdx.y ? g_hn : g_xn;
    const float4* p = (const float4*)(src + (size_t)row * DD);
    float4 a = p[threadIdx.x], b = p[threadIdx.x + 256];
    float acc[1] = {a.x * a.x + a.y * a.y + a.z * a.z + a.w * a.w +
                    b.x * b.x + b.y * b.y + b.z * b.z + b.w * b.w};
    block_reduce<1>(acc);
    float n = sqrtf(fmaxf(acc[0], MINN));
    float sc = (n > MAXN) ? (MAXN / n) : 1.f;
    float4* o = (float4*)(dst + (size_t)row * DD);
    o[threadIdx.x] = make_float4(a.x * sc, a.y * sc, a.z * sc, a.w * sc);
    o[threadIdx.x + 256] = make_float4(b.x * sc, b.y * sc, b.z * sc, b.w * sc);
    if (threadIdx.x == 0) nd[row] = fminf(n, MAXN);
}

__device__ __forceinline__ void proj_coef(float& coef, float& s2) {
    float n = sqrtf(fmaxf(s2, MINN));
    if (n > MAXN) {
        float f = MAXN / n;
        coef *= f;
        s2 *= f * f;
    }
}

__global__ void __launch_bounds__(256) combine_kernel(
    const float* __restrict__ Wh, const float* __restrict__ Ux, const float* __restrict__ bias,
    const float* __restrict__ nhArr, const float* __restrict__ nxArr,
    float* __restrict__ out, int do_gate) {
    int row = blockIdx.x;
    const float4* wr4 = (const float4*)(Wh + (size_t)row * DD);
    const float4* ur4 = (const float4*)(Ux + (size_t)row * DD);
    const float4* bi4 = (const float4*)bias;
    float4 wv[2], uv4[2], bv[2];
    float v[6] = {0.f, 0.f, 0.f, 0.f, 0.f, 0.f};
#pragma unroll
    for (int it = 0; it < 2; it++) {
        int j = threadIdx.x + it * 256;
        float4 w = wr4[j], u = ur4[j], b = bi4[j];
        wv[it] = w; uv4[it] = u; bv[it] = b;
        v[0] += w.x * w.x + w.y * w.y + w.z * w.z + w.w * w.w;
        v[1] += u.x * u.x + u.y * u.y + u.z * u.z + u.w * u.w;
        v[2] += w.x * u.x + w.y * u.y + w.z * u.z + w.w * u.w;
        v[3] += w.x * b.x + w.y * b.y + w.z * b.z + w.w * b.w;
        v[4] += u.x * b.x + u.y * b.y + u.z * b.z + u.w * b.w;
        v[5] += b.x * b.x + b.y * b.y + b.z * b.z + b.w * b.w;
    }
    block_reduce<6>(v);

    float hn = nhArr[row], xn = nxArr[row];

    float Mw = sqrtf(fmaxf(v[0], MINN));
    float cu = tanhf(Mw / hn * artanh_c(hn)) / Mw;
    float su = cu * cu * v[0];
    proj_coef(cu, su);

    float Mu = sqrtf(fmaxf(v[1], MINN));
    float cv = tanhf(Mu / xn * artanh_c(xn)) / Mu;
    float sv = cv * cv * v[1];
    proj_coef(cv, sv);

    float uv = cu * cv * v[2];
    float a = 1.f + 2.f * uv + sv;
    float c = 1.f - su;
    float den = fmaxf(1.f + 2.f * uv + su * sv, MINN);
    float aw = a * cu / den, au = c * cv / den;
    float q2 = aw * aw * v[0] + 2.f * aw * au * v[2] + au * au * v[1];
    {
        float n = sqrtf(fmaxf(q2, MINN));
        if (n > MAXN) { float f = MAXN / n; aw *= f; au *= f; q2 *= f * f; }
    }

    float qb = aw * v[3] + au * v[4];
    float b2 = v[5];
    float A2 = 1.f + 2.f * qb + b2;
    float C2 = 1.f - q2;
    float den2 = fmaxf(1.f + 2.f * qb + q2 * b2, MINN);
    float fw = A2 * aw / den2, fu = A2 * au / den2, fb = C2 / den2;
    float f2 = fw * fw * v[0] + fu * fu * v[1] + fb * fb * v[5] +
               2.f * fw * fu * v[2] + 2.f * fw * fb * v[3] + 2.f * fu * fb * v[4];
    {
        float n = sqrtf(fmaxf(f2, MINN));
        if (n > MAXN) { float f = MAXN / n; fw *= f; fu *= f; fb *= f; f2 *= f * f; }
    }

    float4* o = (float4*)(out + (size_t)row * DD);
    if (do_gate) {
        float fn = sqrtf(fmaxf(f2, MINN));
        float lg = artanh_c(fn) / fn;
#pragma unroll
        for (int it = 0; it < 2; it++) {
            int j = threadIdx.x + it * 256;
            float4 w = wv[it], u = uv4[it], b = bv[it];
            float t0 = lg * (fw * w.x + fu * u.x + fb * b.x);
            float t1 = lg * (fw * w.y + fu * u.y + fb * b.y);
            float t2 = lg * (fw * w.z + fu * u.z + fb * b.z);
            float t3 = lg * (fw * w.w + fu * u.w + fb * b.w);
            o[j] = make_float4(1.f / (1.f + expf(-t0)), 1.f / (1.f + expf(-t1)),
                               1.f / (1.f + expf(-t2)), 1.f / (1.f + expf(-t3)));
        }
    } else {
#pragma unroll
        for (int it = 0; it < 2; it++) {
            int j = threadIdx.x + it * 256;
            float4 w = wv[it], u = uv4[it], b = bv[it];
            o[j] = make_float4(fw * w.x + fu * u.x + fb * b.x, fw * w.y + fu * u.y + fb * b.y,
                               fw * w.z + fu * u.z + fb * b.z, fw * w.w + fu * u.w + fb * b.w);
        }
    }
}

__global__ void __launch_bounds__(256) rpoint_kernel() {
    int row = blockIdx.x;
    const float4* hp4 = (const float4*)(g_hp + (size_t)row * DD);
    const float4* r4 = (const float4*)(g_r + (size_t)row * DD);
    float hn = g_hn[row];
    float ch = artanh_c(hn) / hn;

    float4 hv[2], rv[2];
    float v[1] = {0.f};
#pragma unroll
    for (int it = 0; it < 2; it++) {
        int j = threadIdx.x + it * 256;
        float4 h = hp4[j], r = r4[j];
        hv[it] = h; rv[it] = r;
        float t0 = h.x * r.x, t1 = h.y * r.y, t2 = h.z * r.z, t3 = h.w * r.w;
        v[0] += t0 * t0 + t1 * t1 + t2 * t2 + t3 * t3;
    }
    block_reduce<1>(v);

    float s2 = ch * ch * v[0];
    float nv = sqrtf(fmaxf(s2, MINN));
    float cpf = tanhf(nv) / nv * ch;
    float o2 = cpf * cpf * v[0];
    float on = sqrtf(fmaxf(o2, MINN));
    if (on > MAXN) { cpf *= MAXN / on; on = MAXN; }

    float4* o = (float4*)(g_rph + (size_t)row * DD);
#pragma unroll
    for (int it = 0; it < 2; it++) {
        int j = threadIdx.x + it * 256;
        float4 h = hv[it], r = rv[it];
        o[j] = make_float4(cpf * h.x * r.x, cpf * h.y * r.y, cpf * h.z * r.z, cpf * h.w * r.w);
    }
    if (threadIdx.x == 0) g_rphn[row] = on;
}

__global__ void __launch_bounds__(256) final_kernel(float* __restrict__ out) {
    int row = blockIdx.x;
    const float4* hp4 = (const float4*)(g_hp + (size_t)row * DD);
    const float4* ht4 = (const float4*)(g_ht + (size_t)row * DD);
    const float4* z4 = (const float4*)(g_z + (size_t)row * DD);
    float hn = g_hn[row];
    float u2 = hn * hn;

    float4 hv[2], tv[2], zv[2];
    float v[2] = {0.f, 0.f};
#pragma unroll
    for (int it = 0; it < 2; it++) {
        int j = threadIdx.x + it * 256;
        float4 h = hp4[j], t = ht4[j];
        hv[it] = h; tv[it] = t; zv[it] = z4[j];
        v[0] += h.x * t.x + h.y * t.y + h.z * t.z + h.w * t.w;
        v[1] += t.x * t.x + t.y * t.y + t.z * t.z + t.w * t.w;
    }
    block_reduce<2>(v);

    float uv = -v[0], v2 = v[1];
    float a = 1.f + 2.f * uv + v2;
    float c = 1.f - u2;
    float den = fmaxf(1.f + 2.f * uv + u2 * v2, MINN);
    float mh = -a / den, mt = c / den;
    float m2 = mh * mh * u2 + 2.f * mh * mt * v[0] + mt * mt * v[1];
    {
        float n = sqrtf(fmaxf(m2, MINN));
        if (n > MAXN) { float f = MAXN / n; mh *= f; mt *= f; m2 *= f * f; }
    }
    float mn = sqrtf(fmaxf(m2, MINN));
    float cm = artanh_c(mn) / mn;

    float w[2] = {0.f, 0.f};
#pragma unroll
    for (int it = 0; it < 2; it++) {
        float4 h = hv[it], t = tv[it], z = zv[it];
        float m0 = mh * h.x + mt * t.x, m1 = mh * h.y + mt * t.y;
        float m2e = mh * h.z + mt * t.z, m3 = mh * h.w + mt * t.w;
        float p0 = z.x * m0, p1 = z.y * m1, p2 = z.z * m2e, p3 = z.w * m3;
        w[0] += p0 * p0 + p1 * p1 + p2 * p2 + p3 * p3;
        w[1] += p0 * h.x + p1 * h.y + p2 * h.z + p3 * h.w;
    }
    block_reduce<2>(w);

    float sv2 = cm * cm * w[0];
    float nv = sqrtf(fmaxf(sv2, MINN));
    float cp = tanhf(nv) / nv * cm;
    float p2 = cp * cp * w[0];
    {
        float n = sqrtf(fmaxf(p2, MINN));
        if (n > MAXN) { float f = MAXN / n; cp *= f; p2 *= f * f; }
    }

    float uv2 = cp * w[1];
    float A = 1.f + 2.f * uv2 + p2;
    float C = 1.f - u2;
    float den3 = fmaxf(1.f + 2.f * uv2 + u2 * p2, MINN);
    float chh = A / den3;
    float cpp = C * cp / den3;
    float o2 = chh * chh * u2 + 2.f * chh * cpp * w[1] + cpp * cpp * w[0];
    {
        float n = sqrtf(fmaxf(o2, MINN));
        if (n > MAXN) { float f = MAXN / n; chh *= f; cpp *= f; }
    }

    float4* o = (float4*)(out + (size_t)row * DD);
#pragma unroll
    for (int it = 0; it < 2; it++) {
        int j = threadIdx.x + it * 256;
        float4 h = hv[it], t = tv[it], z = zv[it];
        float m0 = mh * h.x + mt * t.x, m1 = mh * h.y + mt * t.y;
        float m2e = mh * h.z + mt * t.z, m3 = mh * h.w + mt * t.w;
        o[j] = make_float4(chh * h.x + cpp * z.x * m0, chh * h.y + cpp * z.y * m1,
                           chh * h.z + cpp * z.z * m2e, chh * h.w + cpp * z.w * m3);
    }
}

// =================== launch ===================
extern "C" void kernel_launch(void* const* d_in, const int* in_sizes, int n_in,
                              void* d_out, int out_size) {
    (void)in_sizes; (void)n_in; (void)out_size;
    const float* hyp_x = (const float*)d_in[0];
    const float* hidden = (const float*)d_in[1];
    const float* w_z = (const float*)d_in[2];
    const float* w_r = (const float*)d_in[3];
    const float* w_h = (const float*)d_in[4];
    const float* u_z = (const float*)d_in[5];
    const float* u_r = (const float*)d_in[6];
    const float* b_z = (const float*)d_in[7];
    const float* b_r = (const float*)d_in[8];
    const float* b_h = (const float*)d_in[9];
    float* out = (float*)d_out;

    float *xp, *hp, *G0, *G1, *G2, *G3, *G4, *zz, *rr, *rph, *ht, *xn, *hn, *rphn;
    cudaGetSymbolAddress((void**)&xp, g_xp);
    cudaGetSymbolAddress((void**)&hp, g_hp);
    cudaGetSymbolAddress((void**)&G0, g_G0);
    cudaGetSymbolAddress((void**)&G1, g_G1);
    cudaGetSymbolAddress((void**)&G2, g_G2);
    cudaGetSymbolAddress((void**)&G3, g_G3);
    cudaGetSymbolAddress((void**)&G4, g_G4);
    cudaGetSymbolAddress((void**)&zz, g_z);
    cudaGetSymbolAddress((void**)&rr, g_r);
    cudaGetSymbolAddress((void**)&rph, g_rph);
    cudaGetSymbolAddress((void**)&ht, g_ht);
    cudaGetSymbolAddress((void**)&xn, g_xn);
    cudaGetSymbolAddress((void**)&hn, g_hn);
    cudaGetSymbolAddress((void**)&rphn, g_rphn);

    static int smem_set = 0;
    if (!smem_set) {
        cudaFuncSetAttribute(mma_gemm_kernel, cudaFuncAttributeMaxDynamicSharedMemorySize,
                             SMEM_BYTES);
        smem_set = 1;
    }

    // 1. project inputs, record norms
    proj_norm_kernel<<<dim3(BB, 2), 256>>>(hyp_x, hidden);

    // 2. four independent GEMMs (tensor cores, bf16x3 via mma.sync)
    GemmArgs ga;
    ga.A[0] = hp; ga.Bm[0] = w_z; ga.C[0] = G0;
    ga.A[1] = hp; ga.Bm[1] = w_r; ga.C[1] = G1;
    ga.A[2] = xp; ga.Bm[2] = u_z; ga.C[2] = G2;
    ga.A[3] = xp; ga.Bm[3] = u_r; ga.C[3] = G3;
    mma_gemm_kernel<<<dim3(16, 16, 4), 256, SMEM_BYTES>>>(ga);

    // 3. gates z and r
    combine_kernel<<<BB, 256>>>(G0, G2, b_z, hn, xn, zz, 1);
    combine_kernel<<<BB, 256>>>(G1, G3, b_r, hn, xn, rr, 1);

    // 4. r_point_h
    rpoint_kernel<<<BB, 256>>>();

    // 5. GEMM rph @ w_h
    GemmArgs gh;
    gh.A[0] = rph; gh.Bm[0] = w_h; gh.C[0] = G4;
    gh.A[1] = rph; gh.Bm[1] = w_h; gh.C[1] = G4;
    gh.A[2] = rph; gh.Bm[2] = w_h; gh.C[2] = G4;
    gh.A[3] = rph; gh.Bm[3] = w_h; gh.C[3] = G4;
    mma_gemm_kernel<<<dim3(16, 16, 1), 256, SMEM_BYTES>>>(gh);

    // 6. h_tilde (reuses G3 = xp@u_r per reference)
    combine_kernel<<<BB, 256>>>(G4, G3, b_h, rphn, xn, ht, 0);

    // 7. new_h
    final_kernel<<<BB, 256>>>(out);
}